// round 14
// baseline (speedup 1.0000x reference)
#include <cuda_runtime.h>
#include <cuda_fp16.h>
#include <math.h>
#include <stdint.h>

#define S_LEN   2048
#define D_MODEL 1024
#define TRIPLE  (3 * D_MODEL)
#define H_NUM   16
#define HD      64
#define CHUNK   64
#define NCHUNK  (S_LEN / CHUNK)   // 32
#define EPSV    1e-6f

// ---------------- scratch (no allocations allowed) ----------------
__device__ float g_qkv[(size_t)S_LEN * TRIPLE];              // [phi(q) | phi(k) | v] fp32
__device__ float g_state[(size_t)H_NUM * NCHUNK * HD * HD];
__device__ float g_ksum[H_NUM * NCHUNK * HD];

// fp16 GEMM operands (single-term)
__device__ __half g_x_h[(size_t)S_LEN * D_MODEL];
__device__ __half g_wq_h[(size_t)TRIPLE * D_MODEL];    // W_qkv^T [3072,1024]
__device__ __half g_wo_h[(size_t)D_MODEL * D_MODEL];   // W_out^T [1024,1024]
__device__ __half g_at_h[(size_t)S_LEN * D_MODEL];     // attn output

__device__ __forceinline__ float phi_fn(float x) {
    return x > 0.f ? x + 1.f : expf(x);
}

__device__ __forceinline__ uint32_t smem_u32(const void* p) {
    uint32_t a;
    asm("{ .reg .u64 t; cvta.to.shared.u64 t, %1; cvt.u32.u64 %0, t; }" : "=r"(a) : "l"(p));
    return a;
}
__device__ __forceinline__ void cp16(uint32_t s, const void* g) {
    asm volatile("cp.async.cg.shared.global [%0], [%1], 16;" :: "r"(s), "l"(g) : "memory");
}
#define CP_COMMIT() asm volatile("cp.async.commit_group;" ::: "memory")
#define CP_WAIT1()  asm volatile("cp.async.wait_group 1;" ::: "memory")

__device__ __forceinline__ void ldm_x4(uint32_t addr, uint32_t* r) {
    asm volatile("ldmatrix.sync.aligned.m8n8.x4.shared.b16 {%0,%1,%2,%3}, [%4];"
        : "=r"(r[0]), "=r"(r[1]), "=r"(r[2]), "=r"(r[3]) : "r"(addr));
}
__device__ __forceinline__ void mma16816(float* d, const uint32_t* a, uint32_t b0, uint32_t b1) {
    asm volatile("mma.sync.aligned.m16n8k16.row.col.f32.f16.f16.f32 "
        "{%0,%1,%2,%3}, {%4,%5,%6,%7}, {%8,%9}, {%0,%1,%2,%3};"
        : "+f"(d[0]), "+f"(d[1]), "+f"(d[2]), "+f"(d[3])
        : "r"(a[0]), "r"(a[1]), "r"(a[2]), "r"(a[3]), "r"(b0), "r"(b1));
}

// ====================== conversion kernels ======================
__global__ __launch_bounds__(256) void conv_h_kernel(
    const float* __restrict__ X, __half* __restrict__ hi, int n4)
{
    int i = blockIdx.x * 256 + threadIdx.x;
    if (i >= n4) return;
    float4 v = reinterpret_cast<const float4*>(X)[i];
    reinterpret_cast<__half2*>(hi)[i * 2 + 0] =
        __halves2half2(__float2half_rn(v.x), __float2half_rn(v.y));
    reinterpret_cast<__half2*>(hi)[i * 2 + 1] =
        __halves2half2(__float2half_rn(v.z), __float2half_rn(v.w));
}

// transpose + fp16 round: W [R rows, Ccols] -> T[Ccols, R]
__global__ __launch_bounds__(256) void transpose_h_kernel(
    const float* __restrict__ W, __half* __restrict__ Thi, int R, int Ccols)
{
    __shared__ float t[32][33];
    const int tx = threadIdx.x, ty = threadIdx.y;   // 32 x 8
    const int bx = blockIdx.x, by = blockIdx.y;
#pragma unroll
    for (int j = 0; j < 4; j++) {
        int r = by * 32 + ty + j * 8;
        int c = bx * 32 + tx;
        t[ty + j * 8][tx] = W[(size_t)r * Ccols + c];
    }
    __syncthreads();
#pragma unroll
    for (int j = 0; j < 4; j++) {
        int n = bx * 32 + ty + j * 8;
        int k = by * 32 + tx;
        Thi[(size_t)n * R + k] = __float2half_rn(t[tx][ty + j * 8]);
    }
}

// ====================== mma.sync GEMM: C = A @ B^T (fp16, single term) ======================
// 128x128 tile, BK=64, 2-stage, 512 threads, warp tile 32x32 -> 32 warps/SM @ <=64 regs.
#define BK        64
#define NKB       (D_MODEL / BK)          // 16
#define ROW_B     144                      // smem row stride bytes (64 fp16 + 16B pad)
#define TILE_A    (128 * ROW_B)            // 18432
#define TILE_BB   (128 * ROW_B)            // 18432
#define STAGE_B   (TILE_A + TILE_BB)       // 36864: A|B
#define NSTAGE    2
#define GEMM_SMEM (NSTAGE * STAGE_B)       // 73728

__device__ __forceinline__ void issue_stage(
    uint32_t sbase, const __half* pA, const __half* pB, int k0, int tid)
{
    // A and B tiles: 128 rows x 8 chunks = 1024 chunks each, 2 per thread per tile
#pragma unroll
    for (int c = 0; c < 2; c++) {
        const int w = tid + 512 * c;
        const int row = w >> 3, seg = w & 7;
        const uint32_t off = (uint32_t)row * ROW_B + (uint32_t)seg * 16;
        const size_t g = (size_t)row * D_MODEL + k0 + seg * 8;
        cp16(sbase + off, pA + g);
        cp16(sbase + TILE_A + off, pB + g);
    }
}

__global__ __launch_bounds__(512, 2) void gemm1_mma_kernel(
    const __half* __restrict__ Ah, const __half* __restrict__ Bh,
    float* __restrict__ C, int N, int phi_cols)
{
    extern __shared__ char smem_raw[];
    const uint32_t sb = smem_u32(smem_raw);
    const int tid = threadIdx.x;
    const int wid = tid >> 5, lane = tid & 31;
    const int warp_m = wid & 3;     // 4 warps along M, 32 rows each
    const int warp_n = wid >> 2;    // 4 warps along N, 32 cols each
    const int bm = blockIdx.y, bn = blockIdx.x;

    const __half* pA = Ah + (size_t)bm * 128 * D_MODEL;
    const __half* pB = Bh + (size_t)bn * 128 * D_MODEL;

    float acc[2][4][4];
#pragma unroll
    for (int mt = 0; mt < 2; mt++)
#pragma unroll
        for (int q = 0; q < 4; q++)
#pragma unroll
            for (int e = 0; e < 4; e++) acc[mt][q][e] = 0.f;

    // ldmatrix lane -> (row, byte) mapping
    const int aRow  = warp_m * 32 + (lane & 7) + ((lane >> 3) & 1) * 8;  // + mt*16
    const int aByte = (lane >> 4) * 16;                                   // + ks*32
    const int bRow  = warp_n * 32 + (lane & 7) + (lane >> 4) * 8;         // + p*16
    const int bByte = ((lane >> 3) & 1) * 16;                             // + ks*32

    issue_stage(sb + 0 * STAGE_B, pA, pB, 0, tid);  CP_COMMIT();
    issue_stage(sb + 1 * STAGE_B, pA, pB, BK, tid); CP_COMMIT();

    for (int kb = 0; kb < NKB; kb++) {
        CP_WAIT1();              // stage kb resident
        __syncthreads();

        const uint32_t st = sb + (kb & 1) * STAGE_B;
#pragma unroll
        for (int ks = 0; ks < 4; ks++) {      // 4 k16-steps per BK=64 stage
            uint32_t ah[2][4];
#pragma unroll
            for (int mt = 0; mt < 2; mt++) {
                const uint32_t ro = (uint32_t)(aRow + mt * 16) * ROW_B + aByte + ks * 32;
                ldm_x4(st + ro, ah[mt]);
            }
#pragma unroll
            for (int p = 0; p < 2; p++) {
                uint32_t bh[4];
                const uint32_t ro = (uint32_t)(bRow + p * 16) * ROW_B + bByte + ks * 32;
                ldm_x4(st + TILE_A + ro, bh);
#pragma unroll
                for (int mt = 0; mt < 2; mt++)
#pragma unroll
                    for (int h = 0; h < 2; h++) {
                        const int q = p * 2 + h;
                        mma16816(acc[mt][q], ah[mt], bh[h * 2], bh[h * 2 + 1]);
                    }
            }
        }

        __syncthreads();         // all warps done reading this stage
        if (kb + 2 < NKB)
            issue_stage(st, pA, pB, (kb + 2) * BK, tid);
        CP_COMMIT();             // always commit (possibly empty) for exact accounting
    }

    // epilogue: phi + store fp32
    const bool ap = (bn * 128) < phi_cols;
    const int r0 = lane >> 2, c0 = (lane & 3) * 2;
#pragma unroll
    for (int mt = 0; mt < 2; mt++) {
        const int row = bm * 128 + warp_m * 32 + mt * 16 + r0;
#pragma unroll
        for (int q = 0; q < 4; q++) {
            const int col = bn * 128 + warp_n * 32 + q * 8 + c0;
            float2 v0 = make_float2(acc[mt][q][0], acc[mt][q][1]);
            float2 v1 = make_float2(acc[mt][q][2], acc[mt][q][3]);
            if (ap) {
                v0.x = phi_fn(v0.x); v0.y = phi_fn(v0.y);
                v1.x = phi_fn(v1.x); v1.y = phi_fn(v1.y);
            }
            *reinterpret_cast<float2*>(C + (size_t)row * N + col)       = v0;
            *reinterpret_cast<float2*>(C + (size_t)(row + 8) * N + col) = v1;
        }
    }
}

// ---------------- K2: per-(head, chunk) local KV state + k-sum (CHUNK=64) ----------------
__global__ __launch_bounds__(256) void chunk_state_kernel()
{
    __shared__ float Ks[64][64];
    __shared__ float Vs[64][64];
    const int c = blockIdx.x, h = blockIdx.y;
    const int tid = threadIdx.x;
    const int ti = (tid >> 4) * 4;
    const int tj = (tid & 15) * 4;

    float acc[4][4];
#pragma unroll
    for (int a = 0; a < 4; a++)
#pragma unroll
        for (int b = 0; b < 4; b++) acc[a][b] = 0.f;
    float ksum_acc = 0.f;

    const int s0 = c * CHUNK;
    const float* base = g_qkv + (size_t)s0 * TRIPLE + h * HD;
    for (int e = tid; e < 64 * HD; e += 256) {
        const int r = e >> 6, d = e & 63;
        Ks[r][d] = base[(size_t)r * TRIPLE + D_MODEL + d];
        Vs[r][d] = base[(size_t)r * TRIPLE + 2 * D_MODEL + d];
    }
    __syncthreads();
    for (int t = 0; t < 64; t++) {
        float kv[4], vv[4];
#pragma unroll
        for (int a = 0; a < 4; a++) kv[a] = Ks[t][ti + a];
#pragma unroll
        for (int b = 0; b < 4; b++) vv[b] = Vs[t][tj + b];
#pragma unroll
        for (int a = 0; a < 4; a++)
#pragma unroll
            for (int b = 0; b < 4; b++)
                acc[a][b] = fmaf(kv[a], vv[b], acc[a][b]);
    }
    if (tid < HD) {
        for (int t = 0; t < 64; t++) ksum_acc += Ks[t][tid];
    }

    float* st = g_state + (size_t)(h * NCHUNK + c) * HD * HD;
#pragma unroll
    for (int a = 0; a < 4; a++)
#pragma unroll
        for (int b = 0; b < 4; b++)
            st[(ti + a) * HD + tj + b] = acc[a][b];
    if (tid < HD) g_ksum[(h * NCHUNK + c) * HD + tid] = ksum_acc;
}

// ---------------- K3: inclusive prefix over chunks — one thread per element ----------------
__global__ __launch_bounds__(256) void prefix_kernel()
{
    const int idx = blockIdx.x * 256 + threadIdx.x;       // 0..65535
    const int h = idx >> 12;                               // /4096
    const int e = idx & 4095;
    float* p = g_state + (size_t)h * NCHUNK * (HD * HD) + e;
    float run = 0.f;
#pragma unroll
    for (int c = 0; c < NCHUNK; c++) {
        run += p[(size_t)c * (HD * HD)];
        p[(size_t)c * (HD * HD)] = run;
    }
    if (idx < H_NUM * HD) {
        const int h2 = idx >> 6, e2 = idx & 63;
        float* q = g_ksum + h2 * NCHUNK * HD + e2;
        float r2 = 0.f;
#pragma unroll
        for (int c = 0; c < NCHUNK; c++) {
            r2 += q[c * HD];
            q[c * HD] = r2;
        }
    }
}

// ---------------- K4: per-(head, chunk=64) output, two-phase, 512 threads ----------------
__global__ __launch_bounds__(512) void chunk_out_kernel()
{
    extern __shared__ float sm[];
    float* Qs = sm;                         // [64][65] padded
    float* Ks = Qs + 64 * 65;               // [64][64]
    float* Vs = Ks + 64 * 64;               // [64][64]
    float* Sp = Vs + 64 * 64;               // [64][64]
    float* kp = Sp + 64 * 64;               // [64]
    float* Sc = kp + 64;                    // [64][65] padded (scores)

    const int c = blockIdx.x, h = blockIdx.y;
    const int tid = threadIdx.x;
    const int s0 = c * CHUNK;
    const float* base = g_qkv + (size_t)s0 * TRIPLE + h * HD;

    for (int e = tid; e < CHUNK * HD; e += 512) {
        const int r = e >> 6, d = e & 63;
        Qs[r * 65 + d] = base[(size_t)r * TRIPLE + d];
        Ks[e] = base[(size_t)r * TRIPLE + D_MODEL + d];
        Vs[e] = base[(size_t)r * TRIPLE + 2 * D_MODEL + d];
    }
    if (c > 0) {
        const float* st = g_state + (size_t)(h * NCHUNK + c - 1) * HD * HD;
        for (int e = tid; e < HD * HD; e += 512) Sp[e] = st[e];
        if (tid < HD) kp[tid] = g_ksum[(h * NCHUNK + c - 1) * HD + tid];
    } else {
        for (int e = tid; e < HD * HD; e += 512) Sp[e] = 0.f;
        if (tid < HD) kp[tid] = 0.f;
    }
    __syncthreads();

    const int i  = tid & 63;
    const int tg = tid >> 6;    // 0..7: phase-1 t-group / phase-2 j-group

    // ---- Phase 1: scores S[i][t] for 8 t's per thread (8 independent chains)
    {
        float s[8];
#pragma unroll
        for (int tt = 0; tt < 8; tt++) s[tt] = 0.f;
#pragma unroll 4
        for (int d = 0; d < HD; d++) {
            const float qd = Qs[i * 65 + d];             // lanes distinct i -> conflict-free
            const float* krow = Ks + (tg * 8) * 64 + d;  // warp-broadcast reads
#pragma unroll
            for (int tt = 0; tt < 8; tt++)
                s[tt] = fmaf(qd, krow[tt * 64], s[tt]);
        }
#pragma unroll
        for (int tt = 0; tt < 8; tt++) {
            const int t = tg * 8 + tt;
            Sc[i * 65 + t] = (t <= i) ? s[tt] : 0.f;
        }
    }
    __syncthreads();

    // ---- Phase 2: out = S_masked @ V + q @ S_prev
    const int j0 = tg * 8;
    float acc[8];
#pragma unroll
    for (int j = 0; j < 8; j++) acc[j] = 0.f;
    float denom = EPSV;

#pragma unroll 4
    for (int d = 0; d < HD; d++) {
        const float qd = Qs[i * 65 + d];
        denom = fmaf(qd, kp[d], denom);
        const float* sprow = Sp + d * HD + j0;           // warp-broadcast
#pragma unroll
        for (int j = 0; j < 8; j++) acc[j] = fmaf(qd, sprow[j], acc[j]);
    }

    for (int t = 0; t <= i; t++) {
        const float a = Sc[i * 65 + t];                  // lanes distinct i -> conflict-free
        denom += a;
        const float* vrow = Vs + t * HD + j0;            // warp-broadcast
#pragma unroll
        for (int j = 0; j < 8; j++) acc[j] = fmaf(a, vrow[j], acc[j]);
    }

    const float inv = 1.f / denom;
    const size_t obase = (size_t)(s0 + i) * D_MODEL + h * HD + j0;
    __half2* oh = reinterpret_cast<__half2*>(g_at_h + obase);
#pragma unroll
    for (int j = 0; j < 8; j += 2) {
        oh[j >> 1] = __halves2half2(__float2half_rn(acc[j] * inv),
                                    __float2half_rn(acc[j + 1] * inv));
    }
}

// ---------------- launch ----------------
static const int kOutSmemBytes = (64 * 65 + 64 * 64 * 3 + 64 + 64 * 65) * (int)sizeof(float); // 82944

extern "C" void kernel_launch(void* const* d_in, const int* in_sizes, int n_in,
                              void* d_out, int out_size)
{
    (void)in_sizes; (void)n_in; (void)out_size;
    const float* x    = (const float*)d_in[0];
    const float* Wqkv = (const float*)d_in[2];
    const float* Wout = (const float*)d_in[3];
    float* out = (float*)d_out;

    float* qkv_ptr;
    __half *xh, *wqh, *woh, *ath;
    cudaGetSymbolAddress((void**)&qkv_ptr, g_qkv);
    cudaGetSymbolAddress((void**)&xh, g_x_h);
    cudaGetSymbolAddress((void**)&wqh, g_wq_h);
    cudaGetSymbolAddress((void**)&woh, g_wo_h);
    cudaGetSymbolAddress((void**)&ath, g_at_h);

    cudaFuncSetAttribute(chunk_out_kernel,
                         cudaFuncAttributeMaxDynamicSharedMemorySize, kOutSmemBytes);
    cudaFuncSetAttribute(gemm1_mma_kernel,
                         cudaFuncAttributeMaxDynamicSharedMemorySize, GEMM_SMEM);

    // conversions
    conv_h_kernel<<<(S_LEN * D_MODEL / 4 + 255) / 256, 256>>>(x, xh, S_LEN * D_MODEL / 4);
    {
        dim3 b(32, 8);
        dim3 gq(TRIPLE / 32, D_MODEL / 32);
        transpose_h_kernel<<<gq, b>>>(Wqkv, wqh, D_MODEL, TRIPLE);
        dim3 go(D_MODEL / 32, D_MODEL / 32);
        transpose_h_kernel<<<go, b>>>(Wout, woh, D_MODEL, D_MODEL);
    }

    // K1: qkv = x @ W_qkv (HMMA fp16), phi on first 2048 cols — 128x128 tiles, 512 thr
    {
        dim3 g(TRIPLE / 128, S_LEN / 128);  // (24, 16) = 384 CTAs
        gemm1_mma_kernel<<<g, 512, GEMM_SMEM>>>(xh, wqh, qkv_ptr, TRIPLE, 2 * D_MODEL);
    }

    // K2/K3/K4
    dim3 g2(NCHUNK, H_NUM);
    chunk_state_kernel<<<g2, 256>>>();
    prefix_kernel<<<256, 256>>>();
    chunk_out_kernel<<<g2, 512, kOutSmemBytes>>>();

    // K5: out = attn @ W_out (HMMA fp16) — 128x128 tiles, 512 thr
    {
        dim3 g(D_MODEL / 128, S_LEN / 128); // (8, 16) = 128 CTAs
        gemm1_mma_kernel<<<g, 512, GEMM_SMEM>>>(ath, woh, out, D_MODEL, 0);
    }
}

// round 15
// speedup vs baseline: 1.0405x; 1.0405x over previous
#include <cuda_runtime.h>
#include <cuda_fp16.h>
#include <math.h>
#include <stdint.h>

#define S_LEN   2048
#define D_MODEL 1024
#define TRIPLE  (3 * D_MODEL)
#define H_NUM   16
#define HD      64
#define CHUNK   64
#define NCHUNK  (S_LEN / CHUNK)   // 32
#define EPSV    1e-6f

// ---------------- scratch (no allocations allowed) ----------------
__device__ float g_qkv[(size_t)S_LEN * TRIPLE];              // [phi(q) | phi(k) | v] fp32
__device__ float g_state[(size_t)H_NUM * NCHUNK * HD * HD];
__device__ float g_ksum[H_NUM * NCHUNK * HD];

// fp16 GEMM operands (single-term)
__device__ __half g_x_h[(size_t)S_LEN * D_MODEL];
__device__ __half g_wq_h[(size_t)TRIPLE * D_MODEL];    // W_qkv^T [3072,1024]
__device__ __half g_wo_h[(size_t)D_MODEL * D_MODEL];   // W_out^T [1024,1024]
__device__ __half g_at_h[(size_t)S_LEN * D_MODEL];     // attn output

__device__ __forceinline__ float phi_fn(float x) {
    return x > 0.f ? x + 1.f : expf(x);
}

__device__ __forceinline__ uint32_t smem_u32(const void* p) {
    uint32_t a;
    asm("{ .reg .u64 t; cvta.to.shared.u64 t, %1; cvt.u32.u64 %0, t; }" : "=r"(a) : "l"(p));
    return a;
}
__device__ __forceinline__ void cp16(uint32_t s, const void* g) {
    asm volatile("cp.async.cg.shared.global [%0], [%1], 16;" :: "r"(s), "l"(g) : "memory");
}
#define CP_COMMIT() asm volatile("cp.async.commit_group;" ::: "memory")
#define CP_WAIT1()  asm volatile("cp.async.wait_group 1;" ::: "memory")

__device__ __forceinline__ void ldm_x4(uint32_t addr, uint32_t* r) {
    asm volatile("ldmatrix.sync.aligned.m8n8.x4.shared.b16 {%0,%1,%2,%3}, [%4];"
        : "=r"(r[0]), "=r"(r[1]), "=r"(r[2]), "=r"(r[3]) : "r"(addr));
}
__device__ __forceinline__ void mma16816(float* d, const uint32_t* a, uint32_t b0, uint32_t b1) {
    asm volatile("mma.sync.aligned.m16n8k16.row.col.f32.f16.f16.f32 "
        "{%0,%1,%2,%3}, {%4,%5,%6,%7}, {%8,%9}, {%0,%1,%2,%3};"
        : "+f"(d[0]), "+f"(d[1]), "+f"(d[2]), "+f"(d[3])
        : "r"(a[0]), "r"(a[1]), "r"(a[2]), "r"(a[3]), "r"(b0), "r"(b1));
}

// ====================== fused prep kernel ======================
// blocks [0, 2048):            x fp32 -> fp16
// blocks [2048, 5120):         Wqkv [1024,3072] -> T [3072,1024] fp16
// blocks [5120, 6144):         Wout [1024,1024] -> T [1024,1024] fp16
#define NB_X   2048
#define NB_WQ  3072
#define NB_TOT 6144

__device__ __forceinline__ void transpose_tile(
    const float* __restrict__ W, __half* __restrict__ Thi,
    int R, int Ccols, int bx, int by, int tid, float (*t)[33])
{
    const int tx = tid & 31, ty = tid >> 5;   // 32 x 8
#pragma unroll
    for (int j = 0; j < 4; j++) {
        int r = by * 32 + ty + j * 8;
        int c = bx * 32 + tx;
        t[ty + j * 8][tx] = W[(size_t)r * Ccols + c];
    }
    __syncthreads();
#pragma unroll
    for (int j = 0; j < 4; j++) {
        int n = bx * 32 + ty + j * 8;
        int k = by * 32 + tx;
        Thi[(size_t)n * R + k] = __float2half_rn(t[tx][ty + j * 8]);
    }
}

__global__ __launch_bounds__(256) void prep_kernel(
    const float* __restrict__ x, __half* __restrict__ xh,
    const float* __restrict__ Wq, __half* __restrict__ wqh,
    const float* __restrict__ Wo, __half* __restrict__ woh)
{
    __shared__ float t[32][33];
    const int b = blockIdx.x;
    const int tid = threadIdx.x;
    if (b < NB_X) {
        const int i = b * 256 + tid;   // exactly 524288 float4s
        float4 v = reinterpret_cast<const float4*>(x)[i];
        reinterpret_cast<__half2*>(xh)[i * 2 + 0] =
            __halves2half2(__float2half_rn(v.x), __float2half_rn(v.y));
        reinterpret_cast<__half2*>(xh)[i * 2 + 1] =
            __halves2half2(__float2half_rn(v.z), __float2half_rn(v.w));
    } else if (b < NB_X + NB_WQ) {
        const int bb = b - NB_X;
        transpose_tile(Wq, wqh, D_MODEL, TRIPLE, bb % 96, bb / 96, tid, t);
    } else {
        const int bb = b - NB_X - NB_WQ;
        transpose_tile(Wo, woh, D_MODEL, D_MODEL, bb & 31, bb >> 5, tid, t);
    }
}

// ====================== mma.sync GEMM: C = A @ B^T (fp16, single term) ======================
// 128x128 tile, BK=64, 2-stage, 256 threads, warp tile 64x32:
// each B ldmatrix feeds 8 consecutive MMAs (burst amortization), A frags reused 4x.
#define BK        64
#define NKB       (D_MODEL / BK)          // 16
#define ROW_B     144                      // smem row stride bytes (64 fp16 + 16B pad)
#define TILE_A    (128 * ROW_B)            // 18432
#define TILE_BB   (128 * ROW_B)            // 18432
#define STAGE_B   (TILE_A + TILE_BB)       // 36864: A|B
#define NSTAGE    2
#define GEMM_SMEM (NSTAGE * STAGE_B)       // 73728

__device__ __forceinline__ void issue_stage(
    uint32_t sbase, const __half* pA, const __half* pB, int k0, int tid)
{
    // A and B tiles: 128 rows x 8 chunks = 1024 chunks each, 4 per thread per tile
#pragma unroll
    for (int c = 0; c < 4; c++) {
        const int w = tid + 256 * c;
        const int row = w >> 3, seg = w & 7;
        const uint32_t off = (uint32_t)row * ROW_B + (uint32_t)seg * 16;
        const size_t g = (size_t)row * D_MODEL + k0 + seg * 8;
        cp16(sbase + off, pA + g);
        cp16(sbase + TILE_A + off, pB + g);
    }
}

__global__ __launch_bounds__(256, 2) void gemm1_mma_kernel(
    const __half* __restrict__ Ah, const __half* __restrict__ Bh,
    float* __restrict__ C, int N, int phi_cols)
{
    extern __shared__ char smem_raw[];
    const uint32_t sb = smem_u32(smem_raw);
    const int tid = threadIdx.x;
    const int wid = tid >> 5, lane = tid & 31;
    const int warp_m = wid & 1;     // 2 warps along M, 64 rows each
    const int warp_n = wid >> 1;    // 4 warps along N, 32 cols each
    const int bm = blockIdx.y, bn = blockIdx.x;

    const __half* pA = Ah + (size_t)bm * 128 * D_MODEL;
    const __half* pB = Bh + (size_t)bn * 128 * D_MODEL;

    float acc[4][4][4];
#pragma unroll
    for (int mt = 0; mt < 4; mt++)
#pragma unroll
        for (int q = 0; q < 4; q++)
#pragma unroll
            for (int e = 0; e < 4; e++) acc[mt][q][e] = 0.f;

    // ldmatrix lane -> (row, byte) mapping
    const int aRow  = warp_m * 64 + (lane & 7) + ((lane >> 3) & 1) * 8;  // + mt*16
    const int aByte = (lane >> 4) * 16;                                   // + ks*32
    const int bRow  = warp_n * 32 + (lane & 7) + (lane >> 4) * 8;         // + p*16
    const int bByte = ((lane >> 3) & 1) * 16;                             // + ks*32

    issue_stage(sb + 0 * STAGE_B, pA, pB, 0, tid);  CP_COMMIT();
    issue_stage(sb + 1 * STAGE_B, pA, pB, BK, tid); CP_COMMIT();

    for (int kb = 0; kb < NKB; kb++) {
        CP_WAIT1();              // stage kb resident
        __syncthreads();

        const uint32_t st = sb + (kb & 1) * STAGE_B;
#pragma unroll
        for (int ks = 0; ks < 4; ks++) {      // 4 k16-steps per BK=64 stage
            uint32_t ah[4][4];
#pragma unroll
            for (int mt = 0; mt < 4; mt++) {
                const uint32_t ro = (uint32_t)(aRow + mt * 16) * ROW_B + aByte + ks * 32;
                ldm_x4(st + ro, ah[mt]);
            }
#pragma unroll
            for (int p = 0; p < 2; p++) {
                uint32_t bh[4];
                const uint32_t ro = (uint32_t)(bRow + p * 16) * ROW_B + bByte + ks * 32;
                ldm_x4(st + TILE_A + ro, bh);
#pragma unroll
                for (int mt = 0; mt < 4; mt++)
#pragma unroll
                    for (int h = 0; h < 2; h++) {
                        const int q = p * 2 + h;
                        mma16816(acc[mt][q], ah[mt], bh[h * 2], bh[h * 2 + 1]);
                    }
            }
        }

        __syncthreads();         // all warps done reading this stage
        if (kb + 2 < NKB)
            issue_stage(st, pA, pB, (kb + 2) * BK, tid);
        CP_COMMIT();             // always commit (possibly empty) for exact accounting
    }

    // epilogue: phi + store fp32
    const bool ap = (bn * 128) < phi_cols;
    const int r0 = lane >> 2, c0 = (lane & 3) * 2;
#pragma unroll
    for (int mt = 0; mt < 4; mt++) {
        const int row = bm * 128 + warp_m * 64 + mt * 16 + r0;
#pragma unroll
        for (int q = 0; q < 4; q++) {
            const int col = bn * 128 + warp_n * 32 + q * 8 + c0;
            float2 v0 = make_float2(acc[mt][q][0], acc[mt][q][1]);
            float2 v1 = make_float2(acc[mt][q][2], acc[mt][q][3]);
            if (ap) {
                v0.x = phi_fn(v0.x); v0.y = phi_fn(v0.y);
                v1.x = phi_fn(v1.x); v1.y = phi_fn(v1.y);
            }
            *reinterpret_cast<float2*>(C + (size_t)row * N + col)       = v0;
            *reinterpret_cast<float2*>(C + (size_t)(row + 8) * N + col) = v1;
        }
    }
}

// ---------------- K2: per-(head, chunk) local KV state + k-sum (CHUNK=64) ----------------
__global__ __launch_bounds__(256) void chunk_state_kernel()
{
    __shared__ float Ks[64][64];
    __shared__ float Vs[64][64];
    const int c = blockIdx.x, h = blockIdx.y;
    const int tid = threadIdx.x;
    const int ti = (tid >> 4) * 4;
    const int tj = (tid & 15) * 4;

    float acc[4][4];
#pragma unroll
    for (int a = 0; a < 4; a++)
#pragma unroll
        for (int b = 0; b < 4; b++) acc[a][b] = 0.f;
    float ksum_acc = 0.f;

    const int s0 = c * CHUNK;
    const float* base = g_qkv + (size_t)s0 * TRIPLE + h * HD;
    for (int e = tid; e < 64 * HD; e += 256) {
        const int r = e >> 6, d = e & 63;
        Ks[r][d] = base[(size_t)r * TRIPLE + D_MODEL + d];
        Vs[r][d] = base[(size_t)r * TRIPLE + 2 * D_MODEL + d];
    }
    __syncthreads();
    for (int t = 0; t < 64; t++) {
        float kv[4], vv[4];
#pragma unroll
        for (int a = 0; a < 4; a++) kv[a] = Ks[t][ti + a];
#pragma unroll
        for (int b = 0; b < 4; b++) vv[b] = Vs[t][tj + b];
#pragma unroll
        for (int a = 0; a < 4; a++)
#pragma unroll
            for (int b = 0; b < 4; b++)
                acc[a][b] = fmaf(kv[a], vv[b], acc[a][b]);
    }
    if (tid < HD) {
        for (int t = 0; t < 64; t++) ksum_acc += Ks[t][tid];
    }

    float* st = g_state + (size_t)(h * NCHUNK + c) * HD * HD;
#pragma unroll
    for (int a = 0; a < 4; a++)
#pragma unroll
        for (int b = 0; b < 4; b++)
            st[(ti + a) * HD + tj + b] = acc[a][b];
    if (tid < HD) g_ksum[(h * NCHUNK + c) * HD + tid] = ksum_acc;
}

// ---------------- K3: inclusive prefix over chunks — one thread per element ----------------
__global__ __launch_bounds__(256) void prefix_kernel()
{
    const int idx = blockIdx.x * 256 + threadIdx.x;       // 0..65535
    const int h = idx >> 12;                               // /4096
    const int e = idx & 4095;
    float* p = g_state + (size_t)h * NCHUNK * (HD * HD) + e;
    float run = 0.f;
#pragma unroll
    for (int c = 0; c < NCHUNK; c++) {
        run += p[(size_t)c * (HD * HD)];
        p[(size_t)c * (HD * HD)] = run;
    }
    if (idx < H_NUM * HD) {
        const int h2 = idx >> 6, e2 = idx & 63;
        float* q = g_ksum + h2 * NCHUNK * HD + e2;
        float r2 = 0.f;
#pragma unroll
        for (int c = 0; c < NCHUNK; c++) {
            r2 += q[c * HD];
            q[c * HD] = r2;
        }
    }
}

// ---------------- K4: per-(head, chunk=64) output, two-phase, 512 threads ----------------
// Scores alias the Ks buffer (Ks dead after phase 1); Ks is 65-stride padded so
// aliased score reads/writes stay bank-conflict-free. smem 66KB -> 3 blocks/SM.
__global__ __launch_bounds__(512) void chunk_out_kernel()
{
    extern __shared__ float sm[];
    float* Qs = sm;                         // [64][65] padded
    float* Ks = Qs + 64 * 65;               // [64][65] padded (aliased by scores)
    float* Vs = Ks + 64 * 65;               // [64][64]
    float* Sp = Vs + 64 * 64;               // [64][64]
    float* kp = Sp + 64 * 64;               // [64]
    float* Sc = Ks;                         // scores alias Ks

    const int c = blockIdx.x, h = blockIdx.y;
    const int tid = threadIdx.x;
    const int s0 = c * CHUNK;
    const float* base = g_qkv + (size_t)s0 * TRIPLE + h * HD;

    for (int e = tid; e < CHUNK * HD; e += 512) {
        const int r = e >> 6, d = e & 63;
        Qs[r * 65 + d] = base[(size_t)r * TRIPLE + d];
        Ks[r * 65 + d] = base[(size_t)r * TRIPLE + D_MODEL + d];
        Vs[e] = base[(size_t)r * TRIPLE + 2 * D_MODEL + d];
    }
    if (c > 0) {
        const float* st = g_state + (size_t)(h * NCHUNK + c - 1) * HD * HD;
        for (int e = tid; e < HD * HD; e += 512) Sp[e] = st[e];
        if (tid < HD) kp[tid] = g_ksum[(h * NCHUNK + c - 1) * HD + tid];
    } else {
        for (int e = tid; e < HD * HD; e += 512) Sp[e] = 0.f;
        if (tid < HD) kp[tid] = 0.f;
    }
    __syncthreads();

    const int i  = tid & 63;
    const int tg = tid >> 6;    // 0..7: phase-1 t-group / phase-2 j-group

    // ---- Phase 1: scores S[i][t] for 8 t's per thread (8 independent chains)
    float s[8];
#pragma unroll
    for (int tt = 0; tt < 8; tt++) s[tt] = 0.f;
#pragma unroll 4
    for (int d = 0; d < HD; d++) {
        const float qd = Qs[i * 65 + d];             // lanes distinct i -> conflict-free
        const float* krow = Ks + (tg * 8) * 65 + d;  // warp-broadcast reads
#pragma unroll
        for (int tt = 0; tt < 8; tt++)
            s[tt] = fmaf(qd, krow[tt * 65], s[tt]);
    }
    __syncthreads();   // ALL reads of Ks complete before scores overwrite it
#pragma unroll
    for (int tt = 0; tt < 8; tt++) {
        const int t = tg * 8 + tt;
        Sc[i * 65 + t] = (t <= i) ? s[tt] : 0.f;
    }
    __syncthreads();

    // ---- Phase 2: out = S_masked @ V + q @ S_prev
    const int j0 = tg * 8;
    float acc[8];
#pragma unroll
    for (int j = 0; j < 8; j++) acc[j] = 0.f;
    float denom = EPSV;

#pragma unroll 4
    for (int d = 0; d < HD; d++) {
        const float qd = Qs[i * 65 + d];
        denom = fmaf(qd, kp[d], denom);
        const float* sprow = Sp + d * HD + j0;           // warp-broadcast
#pragma unroll
        for (int j = 0; j < 8; j++) acc[j] = fmaf(qd, sprow[j], acc[j]);
    }

    for (int t = 0; t <= i; t++) {
        const float a = Sc[i * 65 + t];                  // lanes distinct i -> conflict-free
        denom += a;
        const float* vrow = Vs + t * HD + j0;            // warp-broadcast
#pragma unroll
        for (int j = 0; j < 8; j++) acc[j] = fmaf(a, vrow[j], acc[j]);
    }

    const float inv = 1.f / denom;
    const size_t obase = (size_t)(s0 + i) * D_MODEL + h * HD + j0;
    __half2* oh = reinterpret_cast<__half2*>(g_at_h + obase);
#pragma unroll
    for (int j = 0; j < 8; j += 2) {
        oh[j >> 1] = __halves2half2(__float2half_rn(acc[j] * inv),
                                    __float2half_rn(acc[j + 1] * inv));
    }
}

// ---------------- launch ----------------
static const int kOutSmemBytes = (64 * 65 * 2 + 64 * 64 * 2 + 64) * (int)sizeof(float); // 66304

extern "C" void kernel_launch(void* const* d_in, const int* in_sizes, int n_in,
                              void* d_out, int out_size)
{
    (void)in_sizes; (void)n_in; (void)out_size;
    const float* x    = (const float*)d_in[0];
    const float* Wqkv = (const float*)d_in[2];
    const float* Wout = (const float*)d_in[3];
    float* out = (float*)d_out;

    float* qkv_ptr;
    __half *xh, *wqh, *woh, *ath;
    cudaGetSymbolAddress((void**)&qkv_ptr, g_qkv);
    cudaGetSymbolAddress((void**)&xh, g_x_h);
    cudaGetSymbolAddress((void**)&wqh, g_wq_h);
    cudaGetSymbolAddress((void**)&woh, g_wo_h);
    cudaGetSymbolAddress((void**)&ath, g_at_h);

    cudaFuncSetAttribute(chunk_out_kernel,
                         cudaFuncAttributeMaxDynamicSharedMemorySize, kOutSmemBytes);
    cudaFuncSetAttribute(gemm1_mma_kernel,
                         cudaFuncAttributeMaxDynamicSharedMemorySize, GEMM_SMEM);

    // fused prep: x conversion + both weight transposes, one launch
    prep_kernel<<<NB_TOT, 256>>>(x, xh, Wqkv, wqh, Wout, woh);

    // K1: qkv = x @ W_qkv (HMMA fp16), phi on first 2048 cols — 128x128 tiles
    {
        dim3 g(TRIPLE / 128, S_LEN / 128);  // (24, 16) = 384 CTAs
        gemm1_mma_kernel<<<g, 256, GEMM_SMEM>>>(xh, wqh, qkv_ptr, TRIPLE, 2 * D_MODEL);
    }

    // K2/K3/K4
    dim3 g2(NCHUNK, H_NUM);
    chunk_state_kernel<<<g2, 256>>>();
    prefix_kernel<<<256, 256>>>();
    chunk_out_kernel<<<g2, 512, kOutSmemBytes>>>();

    // K5: out = attn @ W_out (HMMA fp16) — 128x128 tiles
    {
        dim3 g(D_MODEL / 128, S_LEN / 128); // (8, 16) = 128 CTAs
        gemm1_mma_kernel<<<g, 256, GEMM_SMEM>>>(ath, woh, out, D_MODEL, 0);
    }
}

// round 16
// speedup vs baseline: 1.0704x; 1.0287x over previous
#include <cuda_runtime.h>
#include <cuda_fp16.h>
#include <math.h>
#include <stdint.h>

#define S_LEN   2048
#define D_MODEL 1024
#define TRIPLE  (3 * D_MODEL)
#define H_NUM   16
#define HD      64
#define CHUNK   64
#define NCHUNK  (S_LEN / CHUNK)   // 32
#define EPSV    1e-6f

// ---------------- scratch (no allocations allowed) ----------------
__device__ __half g_qkv[(size_t)S_LEN * TRIPLE];             // [phi(q) | phi(k) | v] fp16
__device__ float g_state[(size_t)H_NUM * NCHUNK * HD * HD];
__device__ float g_ksum[H_NUM * NCHUNK * HD];

// fp16 GEMM operands (single-term)
__device__ __half g_x_h[(size_t)S_LEN * D_MODEL];
__device__ __half g_wq_h[(size_t)TRIPLE * D_MODEL];    // W_qkv^T [3072,1024]
__device__ __half g_wo_h[(size_t)D_MODEL * D_MODEL];   // W_out^T [1024,1024]
__device__ __half g_at_h[(size_t)S_LEN * D_MODEL];     // attn output

__device__ __forceinline__ float phi_fn(float x) {
    return x > 0.f ? x + 1.f : expf(x);
}

__device__ __forceinline__ uint32_t smem_u32(const void* p) {
    uint32_t a;
    asm("{ .reg .u64 t; cvta.to.shared.u64 t, %1; cvt.u32.u64 %0, t; }" : "=r"(a) : "l"(p));
    return a;
}
__device__ __forceinline__ void cp16(uint32_t s, const void* g) {
    asm volatile("cp.async.cg.shared.global [%0], [%1], 16;" :: "r"(s), "l"(g) : "memory");
}
#define CP_COMMIT() asm volatile("cp.async.commit_group;" ::: "memory")
#define CP_WAIT1()  asm volatile("cp.async.wait_group 1;" ::: "memory")

__device__ __forceinline__ void ldm_x4(uint32_t addr, uint32_t* r) {
    asm volatile("ldmatrix.sync.aligned.m8n8.x4.shared.b16 {%0,%1,%2,%3}, [%4];"
        : "=r"(r[0]), "=r"(r[1]), "=r"(r[2]), "=r"(r[3]) : "r"(addr));
}
__device__ __forceinline__ void mma16816(float* d, const uint32_t* a, uint32_t b0, uint32_t b1) {
    asm volatile("mma.sync.aligned.m16n8k16.row.col.f32.f16.f16.f32 "
        "{%0,%1,%2,%3}, {%4,%5,%6,%7}, {%8,%9}, {%0,%1,%2,%3};"
        : "+f"(d[0]), "+f"(d[1]), "+f"(d[2]), "+f"(d[3])
        : "r"(a[0]), "r"(a[1]), "r"(a[2]), "r"(a[3]), "r"(b0), "r"(b1));
}

// ====================== fused prep kernel ======================
#define NB_X   2048
#define NB_WQ  3072
#define NB_TOT 6144

__device__ __forceinline__ void transpose_tile(
    const float* __restrict__ W, __half* __restrict__ Thi,
    int R, int Ccols, int bx, int by, int tid, float (*t)[33])
{
    const int tx = tid & 31, ty = tid >> 5;   // 32 x 8
#pragma unroll
    for (int j = 0; j < 4; j++) {
        int r = by * 32 + ty + j * 8;
        int c = bx * 32 + tx;
        t[ty + j * 8][tx] = W[(size_t)r * Ccols + c];
    }
    __syncthreads();
#pragma unroll
    for (int j = 0; j < 4; j++) {
        int n = bx * 32 + ty + j * 8;
        int k = by * 32 + tx;
        Thi[(size_t)n * R + k] = __float2half_rn(t[tx][ty + j * 8]);
    }
}

__global__ __launch_bounds__(256) void prep_kernel(
    const float* __restrict__ x, __half* __restrict__ xh,
    const float* __restrict__ Wq, __half* __restrict__ wqh,
    const float* __restrict__ Wo, __half* __restrict__ woh)
{
    __shared__ float t[32][33];
    const int b = blockIdx.x;
    const int tid = threadIdx.x;
    if (b < NB_X) {
        const int i = b * 256 + tid;
        float4 v = reinterpret_cast<const float4*>(x)[i];
        reinterpret_cast<__half2*>(xh)[i * 2 + 0] =
            __halves2half2(__float2half_rn(v.x), __float2half_rn(v.y));
        reinterpret_cast<__half2*>(xh)[i * 2 + 1] =
            __halves2half2(__float2half_rn(v.z), __float2half_rn(v.w));
    } else if (b < NB_X + NB_WQ) {
        const int bb = b - NB_X;
        transpose_tile(Wq, wqh, D_MODEL, TRIPLE, bb % 96, bb / 96, tid, t);
    } else {
        const int bb = b - NB_X - NB_WQ;
        transpose_tile(Wo, woh, D_MODEL, D_MODEL, bb & 31, bb >> 5, tid, t);
    }
}

// ====================== mma.sync GEMM: C = A @ B^T (fp16, single term) ======================
// 128x128 tile, BK=64, 2-stage, 256 threads, warp tile 64x32.
// HALF_OUT: write __half (with optional phi) for qkv; else fp32.
#define BK        64
#define NKB       (D_MODEL / BK)          // 16
#define ROW_B     144                      // smem row stride bytes (64 fp16 + 16B pad)
#define TILE_A    (128 * ROW_B)            // 18432
#define TILE_BB   (128 * ROW_B)            // 18432
#define STAGE_B   (TILE_A + TILE_BB)       // 36864: A|B
#define NSTAGE    2
#define GEMM_SMEM (NSTAGE * STAGE_B)       // 73728

__device__ __forceinline__ void issue_stage(
    uint32_t sbase, const __half* pA, const __half* pB, int k0, int tid)
{
#pragma unroll
    for (int c = 0; c < 4; c++) {
        const int w = tid + 256 * c;
        const int row = w >> 3, seg = w & 7;
        const uint32_t off = (uint32_t)row * ROW_B + (uint32_t)seg * 16;
        const size_t g = (size_t)row * D_MODEL + k0 + seg * 8;
        cp16(sbase + off, pA + g);
        cp16(sbase + TILE_A + off, pB + g);
    }
}

template<bool HALF_OUT>
__global__ __launch_bounds__(256, 2) void gemm1_mma_kernel(
    const __half* __restrict__ Ah, const __half* __restrict__ Bh,
    void* __restrict__ Cv, int N, int phi_cols)
{
    extern __shared__ char smem_raw[];
    const uint32_t sb = smem_u32(smem_raw);
    const int tid = threadIdx.x;
    const int wid = tid >> 5, lane = tid & 31;
    const int warp_m = wid & 1;     // 2 warps along M, 64 rows each
    const int warp_n = wid >> 1;    // 4 warps along N, 32 cols each
    const int bm = blockIdx.y, bn = blockIdx.x;

    const __half* pA = Ah + (size_t)bm * 128 * D_MODEL;
    const __half* pB = Bh + (size_t)bn * 128 * D_MODEL;

    float acc[4][4][4];
#pragma unroll
    for (int mt = 0; mt < 4; mt++)
#pragma unroll
        for (int q = 0; q < 4; q++)
#pragma unroll
            for (int e = 0; e < 4; e++) acc[mt][q][e] = 0.f;

    const int aRow  = warp_m * 64 + (lane & 7) + ((lane >> 3) & 1) * 8;  // + mt*16
    const int aByte = (lane >> 4) * 16;                                   // + ks*32
    const int bRow  = warp_n * 32 + (lane & 7) + (lane >> 4) * 8;         // + p*16
    const int bByte = ((lane >> 3) & 1) * 16;                             // + ks*32

    issue_stage(sb + 0 * STAGE_B, pA, pB, 0, tid);  CP_COMMIT();
    issue_stage(sb + 1 * STAGE_B, pA, pB, BK, tid); CP_COMMIT();

    for (int kb = 0; kb < NKB; kb++) {
        CP_WAIT1();
        __syncthreads();

        const uint32_t st = sb + (kb & 1) * STAGE_B;
#pragma unroll
        for (int ks = 0; ks < 4; ks++) {
            uint32_t ah[4][4];
#pragma unroll
            for (int mt = 0; mt < 4; mt++) {
                const uint32_t ro = (uint32_t)(aRow + mt * 16) * ROW_B + aByte + ks * 32;
                ldm_x4(st + ro, ah[mt]);
            }
#pragma unroll
            for (int p = 0; p < 2; p++) {
                uint32_t bh[4];
                const uint32_t ro = (uint32_t)(bRow + p * 16) * ROW_B + bByte + ks * 32;
                ldm_x4(st + TILE_A + ro, bh);
#pragma unroll
                for (int mt = 0; mt < 4; mt++)
#pragma unroll
                    for (int h = 0; h < 2; h++) {
                        const int q = p * 2 + h;
                        mma16816(acc[mt][q], ah[mt], bh[h * 2], bh[h * 2 + 1]);
                    }
            }
        }

        __syncthreads();
        if (kb + 2 < NKB)
            issue_stage(st, pA, pB, (kb + 2) * BK, tid);
        CP_COMMIT();
    }

    // epilogue: phi + store (fp16 or fp32)
    const bool ap = (bn * 128) < phi_cols;
    const int r0 = lane >> 2, c0 = (lane & 3) * 2;
#pragma unroll
    for (int mt = 0; mt < 4; mt++) {
        const int row = bm * 128 + warp_m * 64 + mt * 16 + r0;
#pragma unroll
        for (int q = 0; q < 4; q++) {
            const int col = bn * 128 + warp_n * 32 + q * 8 + c0;
            float2 v0 = make_float2(acc[mt][q][0], acc[mt][q][1]);
            float2 v1 = make_float2(acc[mt][q][2], acc[mt][q][3]);
            if (ap) {
                v0.x = phi_fn(v0.x); v0.y = phi_fn(v0.y);
                v1.x = phi_fn(v1.x); v1.y = phi_fn(v1.y);
            }
            if (HALF_OUT) {
                __half* C = (__half*)Cv;
                *reinterpret_cast<__half2*>(C + (size_t)row * N + col) =
                    __halves2half2(__float2half_rn(v0.x), __float2half_rn(v0.y));
                *reinterpret_cast<__half2*>(C + (size_t)(row + 8) * N + col) =
                    __halves2half2(__float2half_rn(v1.x), __float2half_rn(v1.y));
            } else {
                float* C = (float*)Cv;
                *reinterpret_cast<float2*>(C + (size_t)row * N + col)       = v0;
                *reinterpret_cast<float2*>(C + (size_t)(row + 8) * N + col) = v1;
            }
        }
    }
}

// ---------------- K2: per-(head, chunk) local KV state + k-sum (fp16 qkv in) ----------------
__global__ __launch_bounds__(256) void chunk_state_kernel()
{
    __shared__ float Ks[64][64];
    __shared__ float Vs[64][64];
    const int c = blockIdx.x, h = blockIdx.y;
    const int tid = threadIdx.x;
    const int ti = (tid >> 4) * 4;
    const int tj = (tid & 15) * 4;

    float acc[4][4];
#pragma unroll
    for (int a = 0; a < 4; a++)
#pragma unroll
        for (int b = 0; b < 4; b++) acc[a][b] = 0.f;
    float ksum_acc = 0.f;

    const int s0 = c * CHUNK;
    const __half* base = g_qkv + (size_t)s0 * TRIPLE + h * HD;
    for (int e = tid; e < 64 * 32; e += 256) {
        const int r = e >> 5, dd = (e & 31) * 2;
        __half2 kk = *reinterpret_cast<const __half2*>(base + (size_t)r * TRIPLE + D_MODEL + dd);
        __half2 vv = *reinterpret_cast<const __half2*>(base + (size_t)r * TRIPLE + 2 * D_MODEL + dd);
        float2 kf = __half22float2(kk), vf = __half22float2(vv);
        Ks[r][dd] = kf.x; Ks[r][dd + 1] = kf.y;
        Vs[r][dd] = vf.x; Vs[r][dd + 1] = vf.y;
    }
    __syncthreads();
    for (int t = 0; t < 64; t++) {
        float kv[4], vv[4];
#pragma unroll
        for (int a = 0; a < 4; a++) kv[a] = Ks[t][ti + a];
#pragma unroll
        for (int b = 0; b < 4; b++) vv[b] = Vs[t][tj + b];
#pragma unroll
        for (int a = 0; a < 4; a++)
#pragma unroll
            for (int b = 0; b < 4; b++)
                acc[a][b] = fmaf(kv[a], vv[b], acc[a][b]);
    }
    if (tid < HD) {
        for (int t = 0; t < 64; t++) ksum_acc += Ks[t][tid];
    }

    float* st = g_state + (size_t)(h * NCHUNK + c) * HD * HD;
#pragma unroll
    for (int a = 0; a < 4; a++)
#pragma unroll
        for (int b = 0; b < 4; b++)
            st[(ti + a) * HD + tj + b] = acc[a][b];
    if (tid < HD) g_ksum[(h * NCHUNK + c) * HD + tid] = ksum_acc;
}

// ---------------- K3: prefix over chunks — register-buffered scan ----------------
__global__ __launch_bounds__(256) void prefix_kernel()
{
    const int idx = blockIdx.x * 256 + threadIdx.x;       // 0..65535
    const int h = idx >> 12;
    const int e = idx & 4095;
    float* p = g_state + (size_t)h * NCHUNK * (HD * HD) + e;
    float v[NCHUNK];
#pragma unroll
    for (int c = 0; c < NCHUNK; c++) v[c] = p[(size_t)c * (HD * HD)];   // 32 independent loads
    float run = 0.f;
#pragma unroll
    for (int c = 0; c < NCHUNK; c++) { run += v[c]; v[c] = run; }
#pragma unroll
    for (int c = 0; c < NCHUNK; c++) p[(size_t)c * (HD * HD)] = v[c];
    if (idx < H_NUM * HD) {
        const int h2 = idx >> 6, e2 = idx & 63;
        float* q = g_ksum + h2 * NCHUNK * HD + e2;
        float w[NCHUNK];
#pragma unroll
        for (int c = 0; c < NCHUNK; c++) w[c] = q[c * HD];
        float r2 = 0.f;
#pragma unroll
        for (int c = 0; c < NCHUNK; c++) { r2 += w[c]; w[c] = r2; }
#pragma unroll
        for (int c = 0; c < NCHUNK; c++) q[c * HD] = w[c];
    }
}

// ---------------- K4: per-(head, chunk=64) output, two-phase, 512 threads ----------------
__global__ __launch_bounds__(512) void chunk_out_kernel()
{
    extern __shared__ float sm[];
    float* Qs = sm;                         // [64][65] padded
    float* Ks = Qs + 64 * 65;               // [64][65] padded (aliased by scores)
    float* Vs = Ks + 64 * 65;               // [64][64]
    float* Sp = Vs + 64 * 64;               // [64][64]
    float* kp = Sp + 64 * 64;               // [64]
    float* Sc = Ks;                         // scores alias Ks

    const int c = blockIdx.x, h = blockIdx.y;
    const int tid = threadIdx.x;
    const int s0 = c * CHUNK;
    const __half* base = g_qkv + (size_t)s0 * TRIPLE + h * HD;

    for (int e = tid; e < 64 * 32; e += 512) {
        const int r = e >> 5, dd = (e & 31) * 2;
        const size_t ro = (size_t)r * TRIPLE;
        float2 qf = __half22float2(*reinterpret_cast<const __half2*>(base + ro + dd));
        float2 kf = __half22float2(*reinterpret_cast<const __half2*>(base + ro + D_MODEL + dd));
        float2 vf = __half22float2(*reinterpret_cast<const __half2*>(base + ro + 2 * D_MODEL + dd));
        Qs[r * 65 + dd] = qf.x; Qs[r * 65 + dd + 1] = qf.y;
        Ks[r * 65 + dd] = kf.x; Ks[r * 65 + dd + 1] = kf.y;
        Vs[r * 64 + dd] = vf.x; Vs[r * 64 + dd + 1] = vf.y;
    }
    if (c > 0) {
        const float* st = g_state + (size_t)(h * NCHUNK + c - 1) * HD * HD;
        for (int e = tid; e < HD * HD; e += 512) Sp[e] = st[e];
        if (tid < HD) kp[tid] = g_ksum[(h * NCHUNK + c - 1) * HD + tid];
    } else {
        for (int e = tid; e < HD * HD; e += 512) Sp[e] = 0.f;
        if (tid < HD) kp[tid] = 0.f;
    }
    __syncthreads();

    const int i  = tid & 63;
    const int tg = tid >> 6;

    // ---- Phase 1: scores
    float s[8];
#pragma unroll
    for (int tt = 0; tt < 8; tt++) s[tt] = 0.f;
#pragma unroll 4
    for (int d = 0; d < HD; d++) {
        const float qd = Qs[i * 65 + d];
        const float* krow = Ks + (tg * 8) * 65 + d;
#pragma unroll
        for (int tt = 0; tt < 8; tt++)
            s[tt] = fmaf(qd, krow[tt * 65], s[tt]);
    }
    __syncthreads();   // Ks reads complete before scores overwrite
#pragma unroll
    for (int tt = 0; tt < 8; tt++) {
        const int t = tg * 8 + tt;
        Sc[i * 65 + t] = (t <= i) ? s[tt] : 0.f;
    }
    __syncthreads();

    // ---- Phase 2
    const int j0 = tg * 8;
    float acc[8];
#pragma unroll
    for (int j = 0; j < 8; j++) acc[j] = 0.f;
    float denom = EPSV;

#pragma unroll 4
    for (int d = 0; d < HD; d++) {
        const float qd = Qs[i * 65 + d];
        denom = fmaf(qd, kp[d], denom);
        const float* sprow = Sp + d * HD + j0;
#pragma unroll
        for (int j = 0; j < 8; j++) acc[j] = fmaf(qd, sprow[j], acc[j]);
    }

    for (int t = 0; t <= i; t++) {
        const float a = Sc[i * 65 + t];
        denom += a;
        const float* vrow = Vs + t * HD + j0;
#pragma unroll
        for (int j = 0; j < 8; j++) acc[j] = fmaf(a, vrow[j], acc[j]);
    }

    const float inv = 1.f / denom;
    const size_t obase = (size_t)(s0 + i) * D_MODEL + h * HD + j0;
    __half2* oh = reinterpret_cast<__half2*>(g_at_h + obase);
#pragma unroll
    for (int j = 0; j < 8; j += 2) {
        oh[j >> 1] = __halves2half2(__float2half_rn(acc[j] * inv),
                                    __float2half_rn(acc[j + 1] * inv));
    }
}

// ---------------- launch ----------------
static const int kOutSmemBytes = (64 * 65 * 2 + 64 * 64 * 2 + 64) * (int)sizeof(float); // 66304

extern "C" void kernel_launch(void* const* d_in, const int* in_sizes, int n_in,
                              void* d_out, int out_size)
{
    (void)in_sizes; (void)n_in; (void)out_size;
    const float* x    = (const float*)d_in[0];
    const float* Wqkv = (const float*)d_in[2];
    const float* Wout = (const float*)d_in[3];
    float* out = (float*)d_out;

    __half *qkv_ptr, *xh, *wqh, *woh, *ath;
    cudaGetSymbolAddress((void**)&qkv_ptr, g_qkv);
    cudaGetSymbolAddress((void**)&xh, g_x_h);
    cudaGetSymbolAddress((void**)&wqh, g_wq_h);
    cudaGetSymbolAddress((void**)&woh, g_wo_h);
    cudaGetSymbolAddress((void**)&ath, g_at_h);

    cudaFuncSetAttribute(chunk_out_kernel,
                         cudaFuncAttributeMaxDynamicSharedMemorySize, kOutSmemBytes);
    cudaFuncSetAttribute(gemm1_mma_kernel<true>,
                         cudaFuncAttributeMaxDynamicSharedMemorySize, GEMM_SMEM);
    cudaFuncSetAttribute(gemm1_mma_kernel<false>,
                         cudaFuncAttributeMaxDynamicSharedMemorySize, GEMM_SMEM);

    // fused prep: x conversion + both weight transposes
    prep_kernel<<<NB_TOT, 256>>>(x, xh, Wqkv, wqh, Wout, woh);

    // K1: qkv = x @ W_qkv (HMMA fp16), phi on first 2048 cols, fp16 output
    {
        dim3 g(TRIPLE / 128, S_LEN / 128);  // (24, 16)
        gemm1_mma_kernel<true><<<g, 256, GEMM_SMEM>>>(xh, wqh, qkv_ptr, TRIPLE, 2 * D_MODEL);
    }

    // K2/K3/K4
    dim3 g2(NCHUNK, H_NUM);
    chunk_state_kernel<<<g2, 256>>>();
    prefix_kernel<<<256, 256>>>();
    chunk_out_kernel<<<g2, 512, kOutSmemBytes>>>();

    // K5: out = attn @ W_out (HMMA fp16), fp32 output
    {
        dim3 g(D_MODEL / 128, S_LEN / 128); // (8, 16)
        gemm1_mma_kernel<false><<<g, 256, GEMM_SMEM>>>(ath, woh, out, D_MODEL, 0);
    }
}